// round 6
// baseline (speedup 1.0000x reference)
#include <cuda_runtime.h>
#include <cuda_fp16.h>

#define NN 100000
#define NE 1600000
#define NE_PAD (NE + 4 * NN)      // segments padded to multiples of 5
#define D  48
#define D2 24                     // half2 chunks per feature row (96B)
#define HOPS 10
#define SCAN_BLKS ((NN + 1023) / 1024)   // 98

// ---- scratch (static device globals; no runtime allocation allowed) ----
__device__ int     g_degi[NN];
__device__ float   g_norm[NN];
__device__ int     g_offs[NN + 1];
__device__ int     g_bsum[128];
__device__ int     g_cursor[NN];
__device__ __align__(16) int g_csrc[NE_PAD];      // CSR src by dst (pad = NN)
__device__ __align__(16) __half2 g_hnA[(NN + 1) * D2];  // h*norm ping (row NN = zeros)
__device__ __align__(16) __half2 g_hnB[(NN + 1) * D2];  // h*norm pong

// ---------------------------------------------------------------------
__global__ void k_zero_deg() {
    int i = blockIdx.x * blockDim.x + threadIdx.x;
    if (i < NN) g_degi[i] = 0;
}

__global__ void k_hist(const int* __restrict__ dst) {
    int e = blockIdx.x * blockDim.x + threadIdx.x;
    if (e < NE) atomicAdd(&g_degi[dst[e]], 1);
}

// inclusive scan of degrees padded to multiples of 5
__global__ void k_scan1() {
    __shared__ int sh[1024];
    int tid = threadIdx.x;
    int i = blockIdx.x * 1024 + tid;
    sh[tid] = (i < NN) ? ((g_degi[i] + 4) / 5) * 5 : 0;
    __syncthreads();
#pragma unroll
    for (int off = 1; off < 1024; off <<= 1) {
        int t = (tid >= off) ? sh[tid - off] : 0;
        __syncthreads();
        sh[tid] += t;
        __syncthreads();
    }
    if (i < NN) g_offs[i + 1] = sh[tid];
    if (tid == 1023) g_bsum[blockIdx.x] = sh[1023];
}

__global__ void k_scan2() {
    __shared__ int sh[128];
    int t = threadIdx.x;
    int v = (t < SCAN_BLKS) ? g_bsum[t] : 0;
    sh[t] = v;
    __syncthreads();
#pragma unroll
    for (int off = 1; off < 128; off <<= 1) {
        int u = (t >= off) ? sh[t - off] : 0;
        __syncthreads();
        sh[t] += u;
        __syncthreads();
    }
    if (t < SCAN_BLKS) g_bsum[t] = sh[t] - v;
}

// finalize offs; fused norm + cursor
__global__ void k_scan3() {
    int i = blockIdx.x * blockDim.x + threadIdx.x;
    if (i > NN) return;
    int o;
    if (i == 0) { g_offs[0] = 0; o = 0; }
    else        { o = g_offs[i] + g_bsum[(i - 1) >> 10]; g_offs[i] = o; }
    if (i < NN) {
        g_cursor[i] = o;
        g_norm[i] = rsqrtf(fmaxf((float)g_degi[i], 1.0f));
    }
}

__global__ void k_scatter(const int* __restrict__ src, const int* __restrict__ dst) {
    int e = blockIdx.x * blockDim.x + threadIdx.x;
    if (e >= NE) return;
    int pos = atomicAdd(&g_cursor[dst[e]], 1);
    g_csrc[pos] = src[e];
}

// fill segment tails (<=4 per node) with dummy index NN
__global__ void k_pad() {
    int i = blockIdx.x * blockDim.x + threadIdx.x;
    if (i >= NN) return;
    int p = g_cursor[i];
    int e = g_offs[i + 1];
    for (; p < e; p++) g_csrc[p] = NN;
}

// hnA = half2(features * norm); zero dummy row NN in both buffers
__global__ void k_init(const float2* __restrict__ feat) {
    int i = blockIdx.x * blockDim.x + threadIdx.x;
    if (i >= (NN + 1) * D2) return;
    int node = i / D2;
    if (node == NN) {
        g_hnA[i] = __floats2half2_rn(0.f, 0.f);
        g_hnB[i] = __floats2half2_rn(0.f, 0.f);
        return;
    }
    float n = g_norm[node];
    float2 f = feat[i];
    g_hnA[i] = __floats2half2_rn(f.x * n, f.y * n);
}

// One warp per destination node. Wide-lane gather: row = 96B = 6 x uint4.
// lane -> (group g = lane/6, slot = lane%6); one LDG.128 fetches 5 rows.
// Each lane accumulates 8 features fp32. Fold: read all 4 peer groups from
// the UNMODIFIED accumulator (no step-to-step contamination), then add.
template <int LAST, int RB>
__global__ void __launch_bounds__(256) k_prop(const float4* __restrict__ feat,
                                              float4* __restrict__ out_r) {
    int gw = (blockIdx.x * blockDim.x + threadIdx.x) >> 5;
    if (gw >= NN) return;
    int lane = threadIdx.x & 31;
    int g = lane / 6;          // 0..5 (lanes 30,31 -> group 5 = dummy)
    int slot = lane - g * 6;   // 0..5
    bool realg = g < 5;

    const uint4* __restrict__ hp = (const uint4*)(RB ? g_hnB : g_hnA);
    int beg = g_offs[gw];
    int end = g_offs[gw + 1];

    float v[8];
#pragma unroll
    for (int k = 0; k < 8; k++) v[k] = 0.f;

    auto iter = [&](int e) {
        int s = realg ? __ldg(&g_csrc[e + g]) : NN;
        uint4 q = __ldg(hp + (size_t)s * 6 + slot);
        const __half2* hq = (const __half2*)&q;
#pragma unroll
        for (int k = 0; k < 4; k++) {
            float2 f = __half22float2(hq[k]);
            v[2 * k]     += f.x;
            v[2 * k + 1] += f.y;
        }
    };

    int e = beg;
    for (; e + 5 < end; e += 10) { iter(e); iter(e + 5); }
    if (e < end) iter(e);

    // contamination-free fold: read all peers from the original v, then add.
    // Lanes 0..5 read lanes +6,+12,+18,+24 (groups 1..4). Wrapped reads only
    // pollute lanes >=6, which are discarded.
#pragma unroll
    for (int k = 0; k < 8; k++) {
        float t1 = __shfl_sync(0xFFFFFFFFu, v[k], lane + 6);
        float t2 = __shfl_sync(0xFFFFFFFFu, v[k], lane + 12);
        float t3 = __shfl_sync(0xFFFFFFFFu, v[k], lane + 18);
        float t4 = __shfl_sync(0xFFFFFFFFu, v[k], lane + 24);
        v[k] += (t1 + t2) + (t3 + t4);
    }

    if (lane >= 6) return;
    float nrm = g_norm[gw];
    // this lane owns features [slot*8, slot*8+8)
    float4 fa = feat[(size_t)gw * 12 + slot * 2];
    float4 fb = feat[(size_t)gw * 12 + slot * 2 + 1];
    float o[8];
    o[0] = 0.9f * v[0] * nrm + 0.1f * fa.x;
    o[1] = 0.9f * v[1] * nrm + 0.1f * fa.y;
    o[2] = 0.9f * v[2] * nrm + 0.1f * fa.z;
    o[3] = 0.9f * v[3] * nrm + 0.1f * fa.w;
    o[4] = 0.9f * v[4] * nrm + 0.1f * fb.x;
    o[5] = 0.9f * v[5] * nrm + 0.1f * fb.y;
    o[6] = 0.9f * v[6] * nrm + 0.1f * fb.z;
    o[7] = 0.9f * v[7] * nrm + 0.1f * fb.w;
    if (LAST) {
        out_r[(size_t)gw * 12 + slot * 2]     = make_float4(o[0], o[1], o[2], o[3]);
        out_r[(size_t)gw * 12 + slot * 2 + 1] = make_float4(o[4], o[5], o[6], o[7]);
    } else {
        uint4* ow = (uint4*)(RB ? g_hnA : g_hnB);
        uint4 q;
        __half2* hq = (__half2*)&q;
        hq[0] = __floats2half2_rn(o[0] * nrm, o[1] * nrm);
        hq[1] = __floats2half2_rn(o[2] * nrm, o[3] * nrm);
        hq[2] = __floats2half2_rn(o[4] * nrm, o[5] * nrm);
        hq[3] = __floats2half2_rn(o[6] * nrm, o[7] * nrm);
        ow[(size_t)gw * 6 + slot] = q;
    }
}

// positionwise FFN: rst = relu(h@w1+b1)@w2 + b2 + features
__global__ void k_ffn(const float* __restrict__ h,
                      const float* __restrict__ feat,
                      const float* __restrict__ w1, const float* __restrict__ b1,
                      const float* __restrict__ w2, const float* __restrict__ b2,
                      float* __restrict__ out) {
    __shared__ float s_w1[D * D];
    __shared__ float s_w2[D * D];
    __shared__ float s_b1[D];
    __shared__ float s_b2[D];
    for (int i = threadIdx.x; i < D * D; i += blockDim.x) {
        s_w1[i] = w1[i];
        s_w2[i] = w2[i];
    }
    if (threadIdx.x < D) {
        s_b1[threadIdx.x] = b1[threadIdx.x];
        s_b2[threadIdx.x] = b2[threadIdx.x];
    }
    __syncthreads();

    int node = blockIdx.x * blockDim.x + threadIdx.x;
    if (node >= NN) return;

    float hr[D];
    const float4* hrow = (const float4*)(h + (size_t)node * D);
#pragma unroll
    for (int c = 0; c < D / 4; c++) {
        float4 v = hrow[c];
        hr[c * 4 + 0] = v.x; hr[c * 4 + 1] = v.y;
        hr[c * 4 + 2] = v.z; hr[c * 4 + 3] = v.w;
    }

    float mid[D];
#pragma unroll
    for (int jc = 0; jc < D / 4; jc++) {
        float4 acc = *(const float4*)&s_b1[jc * 4];
#pragma unroll
        for (int k = 0; k < D; k++) {
            float4 w = *(const float4*)&s_w1[k * D + jc * 4];
            float hk = hr[k];
            acc.x += hk * w.x; acc.y += hk * w.y;
            acc.z += hk * w.z; acc.w += hk * w.w;
        }
        mid[jc * 4 + 0] = fmaxf(acc.x, 0.f);
        mid[jc * 4 + 1] = fmaxf(acc.y, 0.f);
        mid[jc * 4 + 2] = fmaxf(acc.z, 0.f);
        mid[jc * 4 + 3] = fmaxf(acc.w, 0.f);
    }

    const float4* frow = (const float4*)(feat + (size_t)node * D);
    float4* orow = (float4*)(out + (size_t)node * D);
#pragma unroll
    for (int jc = 0; jc < D / 4; jc++) {
        float4 acc = *(const float4*)&s_b2[jc * 4];
#pragma unroll
        for (int k = 0; k < D; k++) {
            float4 w = *(const float4*)&s_w2[k * D + jc * 4];
            float mk = mid[k];
            acc.x += mk * w.x; acc.y += mk * w.y;
            acc.z += mk * w.z; acc.w += mk * w.w;
        }
        float4 f = frow[jc];
        orow[jc] = make_float4(acc.x + f.x, acc.y + f.y, acc.z + f.z, acc.w + f.w);
    }
}

// ---------------------------------------------------------------------
extern "C" void kernel_launch(void* const* d_in, const int* in_sizes, int n_in,
                              void* d_out, int out_size) {
    const float* feat = (const float*)d_in[0];
    const int*   src  = (const int*)d_in[1];
    const int*   dst  = (const int*)d_in[2];
    const float* w1   = (const float*)d_in[3];
    const float* b1   = (const float*)d_in[4];
    const float* w2   = (const float*)d_in[5];
    const float* b2   = (const float*)d_in[6];
    float* out = (float*)d_out;

    float* out_rst = out;                    // first output: rst [NN, D]
    float* out_r   = out + (size_t)NN * D;   // second output: r  [NN, D]

    const int T = 256;
    int gN  = (NN + T - 1) / T;
    int gE  = (NE + T - 1) / T;
    int gI  = ((NN + 1) * D2 + T - 1) / T;
    int gW  = (NN * 32 + T - 1) / T;         // warp-per-node grid

    // ---- CSR build (segments padded to multiples of 5) ----
    k_zero_deg<<<gN, T>>>();
    k_hist<<<gE, T>>>(dst);
    k_scan1<<<SCAN_BLKS, 1024>>>();
    k_scan2<<<1, 128>>>();
    k_scan3<<<(NN + 1 + T - 1) / T, T>>>();
    k_scatter<<<gE, T>>>(src, dst);
    k_pad<<<gN, T>>>();

    // ---- propagation ----
    k_init<<<gI, T>>>((const float2*)feat);
    for (int hop = 0; hop < HOPS; hop++) {
        int rb = hop & 1;
        if (hop == HOPS - 1) {
            if (rb) k_prop<1, 1><<<gW, T>>>((const float4*)feat, (float4*)out_r);
            else    k_prop<1, 0><<<gW, T>>>((const float4*)feat, (float4*)out_r);
        } else {
            if (rb) k_prop<0, 1><<<gW, T>>>((const float4*)feat, (float4*)out_r);
            else    k_prop<0, 0><<<gW, T>>>((const float4*)feat, (float4*)out_r);
        }
    }

    // ---- FFN + residual ----
    const int TF = 128;
    k_ffn<<<(NN + TF - 1) / TF, TF>>>(out_r, feat, w1, b1, w2, b2, out_rst);
}

// round 7
// speedup vs baseline: 1.0772x; 1.0772x over previous
#include <cuda_runtime.h>
#include <cuda_fp16.h>

#define NN 100000
#define NE 1600000
#define NE_PAD (NE + 3 * NN)      // segments padded to multiples of 4
#define D  48
#define D2 24                     // half2 chunks per feature row (96B payload)
#define RS 64                     // row stride in half2 (128B padded)
#define HOPS 10
#define SCAN_BLKS ((NN + 1023) / 1024)   // 98

// ---- scratch (static device globals; no runtime allocation allowed) ----
__device__ int     g_degi[NN];
__device__ float   g_norm[NN];
__device__ int     g_offs[NN + 1];
__device__ int     g_bsum[128];
__device__ int     g_cursor[NN];
__device__ __align__(16) int g_csrc[NE_PAD];           // CSR src by dst (pad = NN)
__device__ __align__(16) __half2 g_hnA[(NN + 1) * RS]; // h*norm ping, 128B rows
__device__ __align__(16) __half2 g_hnB[(NN + 1) * RS]; // h*norm pong

// ---------------------------------------------------------------------
__global__ void k_zero_deg() {
    int i = blockIdx.x * blockDim.x + threadIdx.x;
    if (i < NN) g_degi[i] = 0;
}

__global__ void k_hist(const int* __restrict__ dst) {
    int e = blockIdx.x * blockDim.x + threadIdx.x;
    if (e < NE) atomicAdd(&g_degi[dst[e]], 1);
}

// inclusive scan of degrees padded to multiples of 4
__global__ void k_scan1() {
    __shared__ int sh[1024];
    int tid = threadIdx.x;
    int i = blockIdx.x * 1024 + tid;
    sh[tid] = (i < NN) ? ((g_degi[i] + 3) & ~3) : 0;
    __syncthreads();
#pragma unroll
    for (int off = 1; off < 1024; off <<= 1) {
        int t = (tid >= off) ? sh[tid - off] : 0;
        __syncthreads();
        sh[tid] += t;
        __syncthreads();
    }
    if (i < NN) g_offs[i + 1] = sh[tid];
    if (tid == 1023) g_bsum[blockIdx.x] = sh[1023];
}

__global__ void k_scan2() {
    __shared__ int sh[128];
    int t = threadIdx.x;
    int v = (t < SCAN_BLKS) ? g_bsum[t] : 0;
    sh[t] = v;
    __syncthreads();
#pragma unroll
    for (int off = 1; off < 128; off <<= 1) {
        int u = (t >= off) ? sh[t - off] : 0;
        __syncthreads();
        sh[t] += u;
        __syncthreads();
    }
    if (t < SCAN_BLKS) g_bsum[t] = sh[t] - v;
}

// finalize offs; fused norm + cursor
__global__ void k_scan3() {
    int i = blockIdx.x * blockDim.x + threadIdx.x;
    if (i > NN) return;
    int o;
    if (i == 0) { g_offs[0] = 0; o = 0; }
    else        { o = g_offs[i] + g_bsum[(i - 1) >> 10]; g_offs[i] = o; }
    if (i < NN) {
        g_cursor[i] = o;
        g_norm[i] = rsqrtf(fmaxf((float)g_degi[i], 1.0f));
    }
}

__global__ void k_scatter(const int* __restrict__ src, const int* __restrict__ dst) {
    int e = blockIdx.x * blockDim.x + threadIdx.x;
    if (e >= NE) return;
    int pos = atomicAdd(&g_cursor[dst[e]], 1);
    g_csrc[pos] = src[e];
}

// fill segment tails (<=3 per node) with dummy index NN
__global__ void k_pad() {
    int i = blockIdx.x * blockDim.x + threadIdx.x;
    if (i >= NN) return;
    int p = g_cursor[i];
    int e = g_offs[i + 1];
    for (; p < e; p++) g_csrc[p] = NN;
}

// hnA = half2(features * norm) in padded 128B rows; zero dummy row NN
__global__ void k_init(const float2* __restrict__ feat) {
    int i = blockIdx.x * blockDim.x + threadIdx.x;
    if (i >= (NN + 1) * D2) return;
    int node = i / D2;
    int c    = i - node * D2;
    if (node == NN) {
        g_hnA[(size_t)node * RS + c] = __floats2half2_rn(0.f, 0.f);
        g_hnB[(size_t)node * RS + c] = __floats2half2_rn(0.f, 0.f);
        return;
    }
    float n = g_norm[node];
    float2 f = feat[i];
    g_hnA[(size_t)node * RS + c] = __floats2half2_rn(f.x * n, f.y * n);
}

// One warp per destination node; lanes 0..23 own one half2 each of the row
// (row = single 128B line). 4 independent row loads per iteration, unroll 2
// -> up to 8 outstanding gathers per warp. fp32 accumulation; fused APPNP
// combine + renorm epilogue. RB: 0 = read A write B.
template <int LAST, int RB>
__global__ void __launch_bounds__(256) k_prop(const float2* __restrict__ feat,
                                              float2* __restrict__ out_r) {
    int gw = (blockIdx.x * blockDim.x + threadIdx.x) >> 5;
    if (gw >= NN) return;
    int lane = threadIdx.x & 31;
    bool act = lane < D2;
    int idx = act ? lane : 0;

    const __half2* __restrict__ hn = RB ? g_hnB : g_hnA;
    int beg = g_offs[gw];
    int end = g_offs[gw + 1];

    float sx = 0.f, sy = 0.f;
#pragma unroll 2
    for (int e = beg; e < end; e += 4) {
        int4 ss = __ldg((const int4*)&g_csrc[e]);
        __half2 v0 = __ldg(&hn[(size_t)ss.x * RS + idx]);
        __half2 v1 = __ldg(&hn[(size_t)ss.y * RS + idx]);
        __half2 v2 = __ldg(&hn[(size_t)ss.z * RS + idx]);
        __half2 v3 = __ldg(&hn[(size_t)ss.w * RS + idx]);
        float2 f0 = __half22float2(v0);
        float2 f1 = __half22float2(v1);
        float2 f2 = __half22float2(v2);
        float2 f3 = __half22float2(v3);
        sx += (f0.x + f1.x) + (f2.x + f3.x);
        sy += (f0.y + f1.y) + (f2.y + f3.y);
    }

    if (!act) return;
    float nrm = g_norm[gw];
    float2 f = feat[(size_t)gw * D2 + lane];
    float vx = 0.9f * sx * nrm + 0.1f * f.x;
    float vy = 0.9f * sy * nrm + 0.1f * f.y;
    if (LAST) {
        out_r[(size_t)gw * D2 + lane] = make_float2(vx, vy);
    } else {
        __half2* __restrict__ o = RB ? g_hnA : g_hnB;
        o[(size_t)gw * RS + lane] = __floats2half2_rn(vx * nrm, vy * nrm);
    }
}

// positionwise FFN: rst = relu(h@w1+b1)@w2 + b2 + features
__global__ void k_ffn(const float* __restrict__ h,
                      const float* __restrict__ feat,
                      const float* __restrict__ w1, const float* __restrict__ b1,
                      const float* __restrict__ w2, const float* __restrict__ b2,
                      float* __restrict__ out) {
    __shared__ float s_w1[D * D];
    __shared__ float s_w2[D * D];
    __shared__ float s_b1[D];
    __shared__ float s_b2[D];
    for (int i = threadIdx.x; i < D * D; i += blockDim.x) {
        s_w1[i] = w1[i];
        s_w2[i] = w2[i];
    }
    if (threadIdx.x < D) {
        s_b1[threadIdx.x] = b1[threadIdx.x];
        s_b2[threadIdx.x] = b2[threadIdx.x];
    }
    __syncthreads();

    int node = blockIdx.x * blockDim.x + threadIdx.x;
    if (node >= NN) return;

    float hr[D];
    const float4* hrow = (const float4*)(h + (size_t)node * D);
#pragma unroll
    for (int c = 0; c < D / 4; c++) {
        float4 v = hrow[c];
        hr[c * 4 + 0] = v.x; hr[c * 4 + 1] = v.y;
        hr[c * 4 + 2] = v.z; hr[c * 4 + 3] = v.w;
    }

    float mid[D];
#pragma unroll
    for (int jc = 0; jc < D / 4; jc++) {
        float4 acc = *(const float4*)&s_b1[jc * 4];
#pragma unroll
        for (int k = 0; k < D; k++) {
            float4 w = *(const float4*)&s_w1[k * D + jc * 4];
            float hk = hr[k];
            acc.x += hk * w.x; acc.y += hk * w.y;
            acc.z += hk * w.z; acc.w += hk * w.w;
        }
        mid[jc * 4 + 0] = fmaxf(acc.x, 0.f);
        mid[jc * 4 + 1] = fmaxf(acc.y, 0.f);
        mid[jc * 4 + 2] = fmaxf(acc.z, 0.f);
        mid[jc * 4 + 3] = fmaxf(acc.w, 0.f);
    }

    const float4* frow = (const float4*)(feat + (size_t)node * D);
    float4* orow = (float4*)(out + (size_t)node * D);
#pragma unroll
    for (int jc = 0; jc < D / 4; jc++) {
        float4 acc = *(const float4*)&s_b2[jc * 4];
#pragma unroll
        for (int k = 0; k < D; k++) {
            float4 w = *(const float4*)&s_w2[k * D + jc * 4];
            float mk = mid[k];
            acc.x += mk * w.x; acc.y += mk * w.y;
            acc.z += mk * w.z; acc.w += mk * w.w;
        }
        float4 f = frow[jc];
        orow[jc] = make_float4(acc.x + f.x, acc.y + f.y, acc.z + f.z, acc.w + f.w);
    }
}

// ---------------------------------------------------------------------
extern "C" void kernel_launch(void* const* d_in, const int* in_sizes, int n_in,
                              void* d_out, int out_size) {
    const float* feat = (const float*)d_in[0];
    const int*   src  = (const int*)d_in[1];
    const int*   dst  = (const int*)d_in[2];
    const float* w1   = (const float*)d_in[3];
    const float* b1   = (const float*)d_in[4];
    const float* w2   = (const float*)d_in[5];
    const float* b2   = (const float*)d_in[6];
    float* out = (float*)d_out;

    float* out_rst = out;                    // first output: rst [NN, D]
    float* out_r   = out + (size_t)NN * D;   // second output: r  [NN, D]

    const int T = 256;
    int gN  = (NN + T - 1) / T;
    int gE  = (NE + T - 1) / T;
    int gI  = ((NN + 1) * D2 + T - 1) / T;
    int gW  = (NN * 32 + T - 1) / T;         // warp-per-node grid

    // ---- CSR build (segments padded to multiples of 4) ----
    k_zero_deg<<<gN, T>>>();
    k_hist<<<gE, T>>>(dst);
    k_scan1<<<SCAN_BLKS, 1024>>>();
    k_scan2<<<1, 128>>>();
    k_scan3<<<(NN + 1 + T - 1) / T, T>>>();
    k_scatter<<<gE, T>>>(src, dst);
    k_pad<<<gN, T>>>();

    // ---- propagation ----
    k_init<<<gI, T>>>((const float2*)feat);
    for (int hop = 0; hop < HOPS; hop++) {
        int rb = hop & 1;
        if (hop == HOPS - 1) {
            if (rb) k_prop<1, 1><<<gW, T>>>((const float2*)feat, (float2*)out_r);
            else    k_prop<1, 0><<<gW, T>>>((const float2*)feat, (float2*)out_r);
        } else {
            if (rb) k_prop<0, 1><<<gW, T>>>((const float2*)feat, (float2*)out_r);
            else    k_prop<0, 0><<<gW, T>>>((const float2*)feat, (float2*)out_r);
        }
    }

    // ---- FFN + residual ----
    const int TF = 128;
    k_ffn<<<(NN + TF - 1) / TF, TF>>>(out_r, feat, w1, b1, w2, b2, out_rst);
}

// round 8
// speedup vs baseline: 1.1130x; 1.0333x over previous
#include <cuda_runtime.h>
#include <cuda_fp16.h>

#define NN 100000
#define NE 1600000
#define NE_PAD (NE + 7 * NN)      // segments padded to multiples of 8
#define D  48
#define D2 24                     // half2 chunks per feature row (96B packed)
#define HOPS 10
#define SCAN_BLKS ((NN + 1023) / 1024)   // 98

// ---- scratch (static device globals; no runtime allocation allowed) ----
__device__ int     g_degi[NN];
__device__ float   g_norm[NN];
__device__ int     g_offs[NN + 1];
__device__ int     g_bsum[128];
__device__ int     g_cursor[NN];
__device__ __align__(16) int g_csrc[NE_PAD];            // CSR src by dst (pad = NN)
__device__ __align__(16) __half2 g_hnA[(NN + 1) * D2];  // h*norm ping (row NN zeros)
__device__ __align__(16) __half2 g_hnB[(NN + 1) * D2];  // h*norm pong

// ---------------------------------------------------------------------
__global__ void k_zero_deg() {
    int i = blockIdx.x * blockDim.x + threadIdx.x;
    if (i < NN) g_degi[i] = 0;
}

__global__ void k_hist(const int* __restrict__ dst) {
    int e = blockIdx.x * blockDim.x + threadIdx.x;
    if (e < NE) atomicAdd(&g_degi[dst[e]], 1);
}

// inclusive scan of degrees padded to multiples of 8
__global__ void k_scan1() {
    __shared__ int sh[1024];
    int tid = threadIdx.x;
    int i = blockIdx.x * 1024 + tid;
    sh[tid] = (i < NN) ? ((g_degi[i] + 7) & ~7) : 0;
    __syncthreads();
#pragma unroll
    for (int off = 1; off < 1024; off <<= 1) {
        int t = (tid >= off) ? sh[tid - off] : 0;
        __syncthreads();
        sh[tid] += t;
        __syncthreads();
    }
    if (i < NN) g_offs[i + 1] = sh[tid];
    if (tid == 1023) g_bsum[blockIdx.x] = sh[1023];
}

// finalize offs (each block redundantly scans the 98 block sums in shared);
// fused norm + cursor
__global__ void k_scan3() {
    __shared__ int sb[128];
    int tid = threadIdx.x;
    if (tid < 128) {
        int v = (tid < SCAN_BLKS) ? g_bsum[tid] : 0;
        sb[tid] = v;
    }
    __syncthreads();
    // exclusive scan of sb in shared (done by first 128 threads)
    if (tid < 128) {
        int v = sb[tid];
#pragma unroll
        for (int off = 1; off < 128; off <<= 1) {
            int u = (tid >= off) ? sb[tid - off] : 0;
            __syncthreads();
            sb[tid] += u;
            __syncthreads();
        }
        sb[tid] -= v;   // exclusive
    } else {
#pragma unroll
        for (int off = 1; off < 128; off <<= 1) { __syncthreads(); __syncthreads(); }
    }
    __syncthreads();

    int i = blockIdx.x * blockDim.x + tid;
    if (i > NN) return;
    int o;
    if (i == 0) { g_offs[0] = 0; o = 0; }
    else        { o = g_offs[i] + sb[(i - 1) >> 10]; g_offs[i] = o; }
    if (i < NN) {
        g_cursor[i] = o;
        g_norm[i] = rsqrtf(fmaxf((float)g_degi[i], 1.0f));
    }
}

__global__ void k_scatter(const int* __restrict__ src, const int* __restrict__ dst) {
    int e = blockIdx.x * blockDim.x + threadIdx.x;
    if (e >= NE) return;
    int pos = atomicAdd(&g_cursor[dst[e]], 1);
    g_csrc[pos] = src[e];
}

// fused: (a) fill segment tails (<=7 per node) with dummy index NN,
//        (b) hnA = half2(features * norm), zero dummy row NN in both buffers
__global__ void k_initpad(const float2* __restrict__ feat) {
    int i = blockIdx.x * blockDim.x + threadIdx.x;
    if (i < NN) {
        int p = g_cursor[i];
        int e = g_offs[i + 1];
        for (; p < e; p++) g_csrc[p] = NN;
    }
    if (i >= (NN + 1) * D2) return;
    int node = i / D2;
    if (node == NN) {
        g_hnA[i] = __floats2half2_rn(0.f, 0.f);
        g_hnB[i] = __floats2half2_rn(0.f, 0.f);
        return;
    }
    float n = g_norm[node];
    float2 f = feat[i];
    g_hnA[i] = __floats2half2_rn(f.x * n, f.y * n);
}

// One warp per destination node; lanes 0..23 own one half2 each of the
// packed 96B row. 8 independent row loads per iteration (two int4 index
// loads) -> deep MLP against L2 latency. fp32 accumulation; fused APPNP
// combine + renorm epilogue. RB: 0 = read A write B.
template <int LAST, int RB>
__global__ void __launch_bounds__(256) k_prop(const float2* __restrict__ feat,
                                              float2* __restrict__ out_r) {
    int gw = (blockIdx.x * blockDim.x + threadIdx.x) >> 5;
    if (gw >= NN) return;
    int lane = threadIdx.x & 31;
    bool act = lane < D2;
    int idx = act ? lane : 0;

    const __half2* __restrict__ hn = RB ? g_hnB : g_hnA;
    int beg = g_offs[gw];
    int end = g_offs[gw + 1];

    float sx = 0.f, sy = 0.f;
    for (int e = beg; e < end; e += 8) {
        int4 sa = __ldg((const int4*)&g_csrc[e]);
        int4 sb = __ldg((const int4*)&g_csrc[e + 4]);
        __half2 v0 = __ldg(&hn[(size_t)sa.x * D2 + idx]);
        __half2 v1 = __ldg(&hn[(size_t)sa.y * D2 + idx]);
        __half2 v2 = __ldg(&hn[(size_t)sa.z * D2 + idx]);
        __half2 v3 = __ldg(&hn[(size_t)sa.w * D2 + idx]);
        __half2 v4 = __ldg(&hn[(size_t)sb.x * D2 + idx]);
        __half2 v5 = __ldg(&hn[(size_t)sb.y * D2 + idx]);
        __half2 v6 = __ldg(&hn[(size_t)sb.z * D2 + idx]);
        __half2 v7 = __ldg(&hn[(size_t)sb.w * D2 + idx]);
        float2 f0 = __half22float2(v0);
        float2 f1 = __half22float2(v1);
        float2 f2 = __half22float2(v2);
        float2 f3 = __half22float2(v3);
        float2 f4 = __half22float2(v4);
        float2 f5 = __half22float2(v5);
        float2 f6 = __half22float2(v6);
        float2 f7 = __half22float2(v7);
        sx += ((f0.x + f1.x) + (f2.x + f3.x)) + ((f4.x + f5.x) + (f6.x + f7.x));
        sy += ((f0.y + f1.y) + (f2.y + f3.y)) + ((f4.y + f5.y) + (f6.y + f7.y));
    }

    if (!act) return;
    float nrm = g_norm[gw];
    float2 f = feat[(size_t)gw * D2 + lane];
    float vx = 0.9f * sx * nrm + 0.1f * f.x;
    float vy = 0.9f * sy * nrm + 0.1f * f.y;
    if (LAST) {
        out_r[(size_t)gw * D2 + lane] = make_float2(vx, vy);
    } else {
        __half2* __restrict__ o = RB ? g_hnA : g_hnB;
        o[(size_t)gw * D2 + lane] = __floats2half2_rn(vx * nrm, vy * nrm);
    }
}

// positionwise FFN: rst = relu(h@w1+b1)@w2 + b2 + features
__global__ void k_ffn(const float* __restrict__ h,
                      const float* __restrict__ feat,
                      const float* __restrict__ w1, const float* __restrict__ b1,
                      const float* __restrict__ w2, const float* __restrict__ b2,
                      float* __restrict__ out) {
    __shared__ float s_w1[D * D];
    __shared__ float s_w2[D * D];
    __shared__ float s_b1[D];
    __shared__ float s_b2[D];
    for (int i = threadIdx.x; i < D * D; i += blockDim.x) {
        s_w1[i] = w1[i];
        s_w2[i] = w2[i];
    }
    if (threadIdx.x < D) {
        s_b1[threadIdx.x] = b1[threadIdx.x];
        s_b2[threadIdx.x] = b2[threadIdx.x];
    }
    __syncthreads();

    int node = blockIdx.x * blockDim.x + threadIdx.x;
    if (node >= NN) return;

    float hr[D];
    const float4* hrow = (const float4*)(h + (size_t)node * D);
#pragma unroll
    for (int c = 0; c < D / 4; c++) {
        float4 v = hrow[c];
        hr[c * 4 + 0] = v.x; hr[c * 4 + 1] = v.y;
        hr[c * 4 + 2] = v.z; hr[c * 4 + 3] = v.w;
    }

    float mid[D];
#pragma unroll
    for (int jc = 0; jc < D / 4; jc++) {
        float4 acc = *(const float4*)&s_b1[jc * 4];
#pragma unroll
        for (int k = 0; k < D; k++) {
            float4 w = *(const float4*)&s_w1[k * D + jc * 4];
            float hk = hr[k];
            acc.x += hk * w.x; acc.y += hk * w.y;
            acc.z += hk * w.z; acc.w += hk * w.w;
        }
        mid[jc * 4 + 0] = fmaxf(acc.x, 0.f);
        mid[jc * 4 + 1] = fmaxf(acc.y, 0.f);
        mid[jc * 4 + 2] = fmaxf(acc.z, 0.f);
        mid[jc * 4 + 3] = fmaxf(acc.w, 0.f);
    }

    const float4* frow = (const float4*)(feat + (size_t)node * D);
    float4* orow = (float4*)(out + (size_t)node * D);
#pragma unroll
    for (int jc = 0; jc < D / 4; jc++) {
        float4 acc = *(const float4*)&s_b2[jc * 4];
#pragma unroll
        for (int k = 0; k < D; k++) {
            float4 w = *(const float4*)&s_w2[k * D + jc * 4];
            float mk = mid[k];
            acc.x += mk * w.x; acc.y += mk * w.y;
            acc.z += mk * w.z; acc.w += mk * w.w;
        }
        float4 f = frow[jc];
        orow[jc] = make_float4(acc.x + f.x, acc.y + f.y, acc.z + f.z, acc.w + f.w);
    }
}

// ---------------------------------------------------------------------
extern "C" void kernel_launch(void* const* d_in, const int* in_sizes, int n_in,
                              void* d_out, int out_size) {
    const float* feat = (const float*)d_in[0];
    const int*   src  = (const int*)d_in[1];
    const int*   dst  = (const int*)d_in[2];
    const float* w1   = (const float*)d_in[3];
    const float* b1   = (const float*)d_in[4];
    const float* w2   = (const float*)d_in[5];
    const float* b2   = (const float*)d_in[6];
    float* out = (float*)d_out;

    float* out_rst = out;                    // first output: rst [NN, D]
    float* out_r   = out + (size_t)NN * D;   // second output: r  [NN, D]

    const int T = 256;
    int gN  = (NN + T - 1) / T;
    int gE  = (NE + T - 1) / T;
    int gI  = ((NN + 1) * D2 + T - 1) / T;
    int gW  = (NN * 32 + T - 1) / T;         // warp-per-node grid

    // ---- CSR build (segments padded to multiples of 8) ----
    k_zero_deg<<<gN, T>>>();
    k_hist<<<gE, T>>>(dst);
    k_scan1<<<SCAN_BLKS, 1024>>>();
    k_scan3<<<(NN + 1 + T - 1) / T, T>>>();
    k_scatter<<<gE, T>>>(src, dst);
    k_initpad<<<gI, T>>>((const float2*)feat);

    // ---- propagation ----
    for (int hop = 0; hop < HOPS; hop++) {
        int rb = hop & 1;
        if (hop == HOPS - 1) {
            if (rb) k_prop<1, 1><<<gW, T>>>((const float2*)feat, (float2*)out_r);
            else    k_prop<1, 0><<<gW, T>>>((const float2*)feat, (float2*)out_r);
        } else {
            if (rb) k_prop<0, 1><<<gW, T>>>((const float2*)feat, (float2*)out_r);
            else    k_prop<0, 0><<<gW, T>>>((const float2*)feat, (float2*)out_r);
        }
    }

    // ---- FFN + residual ----
    const int TF = 128;
    k_ffn<<<(NN + TF - 1) / TF, TF>>>(out_r, feat, w1, b1, w2, b2, out_rst);
}

// round 9
// speedup vs baseline: 1.1562x; 1.0388x over previous
#include <cuda_runtime.h>
#include <cuda_fp16.h>

#define NN 100000
#define NE 1600000
#define NE_PAD (NE + 3 * NN)      // segments padded to multiples of 4
#define D  48
#define D2 24                     // half2 chunks per feature row (96B packed)
#define HOPS 10
#define SCAN_BLKS ((NN + 1023) / 1024)   // 98

// ---- scratch (static device globals; no runtime allocation allowed) ----
__device__ int     g_degi[NN];
__device__ float   g_norm[NN];
__device__ int     g_offs[NN + 1];
__device__ int     g_bsum[128];
__device__ int     g_cursor[NN];
__device__ __align__(16) int g_csrc[NE_PAD];            // CSR src by dst (pad = NN)
__device__ __align__(16) __half2 g_hnA[(NN + 1) * D2];  // h*norm ping (row NN zeros)
__device__ __align__(16) __half2 g_hnB[(NN + 1) * D2];  // h*norm pong

// ---------------------------------------------------------------------
__global__ void k_zero_deg() {
    int i = blockIdx.x * blockDim.x + threadIdx.x;
    if (i < NN) g_degi[i] = 0;
}

__global__ void k_hist(const int* __restrict__ dst) {
    int e = blockIdx.x * blockDim.x + threadIdx.x;
    if (e < NE) atomicAdd(&g_degi[dst[e]], 1);
}

// inclusive scan of degrees padded to multiples of 4
__global__ void k_scan1() {
    __shared__ int sh[1024];
    int tid = threadIdx.x;
    int i = blockIdx.x * 1024 + tid;
    sh[tid] = (i < NN) ? ((g_degi[i] + 3) & ~3) : 0;
    __syncthreads();
#pragma unroll
    for (int off = 1; off < 1024; off <<= 1) {
        int t = (tid >= off) ? sh[tid - off] : 0;
        __syncthreads();
        sh[tid] += t;
        __syncthreads();
    }
    if (i < NN) g_offs[i + 1] = sh[tid];
    if (tid == 1023) g_bsum[blockIdx.x] = sh[1023];
}

// finalize offs (each block redundantly scans the 98 block sums in shared);
// fused norm + cursor. Replaces separate scan2+scan3 kernels.
__global__ void k_scan3() {
    __shared__ int sb[128];
    int tid = threadIdx.x;
    if (tid < 128) {
        int v = (tid < SCAN_BLKS) ? g_bsum[tid] : 0;
        sb[tid] = v;
    }
    __syncthreads();
    if (tid < 128) {
        int v = sb[tid];
#pragma unroll
        for (int off = 1; off < 128; off <<= 1) {
            int u = (tid >= off) ? sb[tid - off] : 0;
            __syncthreads();
            sb[tid] += u;
            __syncthreads();
        }
        sb[tid] -= v;   // exclusive
    } else {
#pragma unroll
        for (int off = 1; off < 128; off <<= 1) { __syncthreads(); __syncthreads(); }
    }
    __syncthreads();

    int i = blockIdx.x * blockDim.x + tid;
    if (i > NN) return;
    int o;
    if (i == 0) { g_offs[0] = 0; o = 0; }
    else        { o = g_offs[i] + sb[(i - 1) >> 10]; g_offs[i] = o; }
    if (i < NN) {
        g_cursor[i] = o;
        g_norm[i] = rsqrtf(fmaxf((float)g_degi[i], 1.0f));
    }
}

__global__ void k_scatter(const int* __restrict__ src, const int* __restrict__ dst) {
    int e = blockIdx.x * blockDim.x + threadIdx.x;
    if (e >= NE) return;
    int pos = atomicAdd(&g_cursor[dst[e]], 1);
    g_csrc[pos] = src[e];
}

// fused: (a) fill segment tails (<=3 per node) with dummy index NN,
//        (b) hnA = half2(features * norm), zero dummy row NN in both buffers
__global__ void k_initpad(const float2* __restrict__ feat) {
    int i = blockIdx.x * blockDim.x + threadIdx.x;
    if (i < NN) {
        int p = g_cursor[i];
        int e = g_offs[i + 1];
        for (; p < e; p++) g_csrc[p] = NN;
    }
    if (i >= (NN + 1) * D2) return;
    int node = i / D2;
    if (node == NN) {
        g_hnA[i] = __floats2half2_rn(0.f, 0.f);
        g_hnB[i] = __floats2half2_rn(0.f, 0.f);
        return;
    }
    float n = g_norm[node];
    float2 f = feat[i];
    g_hnA[i] = __floats2half2_rn(f.x * n, f.y * n);
}

// One warp per destination node; lanes 0..23 own one half2 each of the
// packed 96B row. 4 independent row loads per iteration; fp32 accumulation;
// fused APPNP combine + renorm epilogue. RB: 0 = read A write B.
// (Exact R4 structure — empirically the fastest of all gather variants.)
template <int LAST, int RB>
__global__ void __launch_bounds__(256) k_prop(const float2* __restrict__ feat,
                                              float2* __restrict__ out_r) {
    int gw = (blockIdx.x * blockDim.x + threadIdx.x) >> 5;
    if (gw >= NN) return;
    int lane = threadIdx.x & 31;
    bool act = lane < D2;
    int idx = act ? lane : 0;

    const __half2* __restrict__ hn = RB ? g_hnB : g_hnA;
    int beg = g_offs[gw];
    int end = g_offs[gw + 1];

    float sx = 0.f, sy = 0.f;
    for (int e = beg; e < end; e += 4) {
        int4 ss = __ldg((const int4*)&g_csrc[e]);
        __half2 v0 = __ldg(&hn[(size_t)ss.x * D2 + idx]);
        __half2 v1 = __ldg(&hn[(size_t)ss.y * D2 + idx]);
        __half2 v2 = __ldg(&hn[(size_t)ss.z * D2 + idx]);
        __half2 v3 = __ldg(&hn[(size_t)ss.w * D2 + idx]);
        float2 f0 = __half22float2(v0);
        float2 f1 = __half22float2(v1);
        float2 f2 = __half22float2(v2);
        float2 f3 = __half22float2(v3);
        sx += (f0.x + f1.x) + (f2.x + f3.x);
        sy += (f0.y + f1.y) + (f2.y + f3.y);
    }

    if (!act) return;
    float nrm = g_norm[gw];
    float2 f = feat[(size_t)gw * D2 + lane];
    float vx = 0.9f * sx * nrm + 0.1f * f.x;
    float vy = 0.9f * sy * nrm + 0.1f * f.y;
    if (LAST) {
        out_r[(size_t)gw * D2 + lane] = make_float2(vx, vy);
    } else {
        __half2* __restrict__ o = RB ? g_hnA : g_hnB;
        o[(size_t)gw * D2 + lane] = __floats2half2_rn(vx * nrm, vy * nrm);
    }
}

// positionwise FFN: rst = relu(h@w1+b1)@w2 + b2 + features
__global__ void k_ffn(const float* __restrict__ h,
                      const float* __restrict__ feat,
                      const float* __restrict__ w1, const float* __restrict__ b1,
                      const float* __restrict__ w2, const float* __restrict__ b2,
                      float* __restrict__ out) {
    __shared__ float s_w1[D * D];
    __shared__ float s_w2[D * D];
    __shared__ float s_b1[D];
    __shared__ float s_b2[D];
    for (int i = threadIdx.x; i < D * D; i += blockDim.x) {
        s_w1[i] = w1[i];
        s_w2[i] = w2[i];
    }
    if (threadIdx.x < D) {
        s_b1[threadIdx.x] = b1[threadIdx.x];
        s_b2[threadIdx.x] = b2[threadIdx.x];
    }
    __syncthreads();

    int node = blockIdx.x * blockDim.x + threadIdx.x;
    if (node >= NN) return;

    float hr[D];
    const float4* hrow = (const float4*)(h + (size_t)node * D);
#pragma unroll
    for (int c = 0; c < D / 4; c++) {
        float4 v = hrow[c];
        hr[c * 4 + 0] = v.x; hr[c * 4 + 1] = v.y;
        hr[c * 4 + 2] = v.z; hr[c * 4 + 3] = v.w;
    }

    float mid[D];
#pragma unroll
    for (int jc = 0; jc < D / 4; jc++) {
        float4 acc = *(const float4*)&s_b1[jc * 4];
#pragma unroll
        for (int k = 0; k < D; k++) {
            float4 w = *(const float4*)&s_w1[k * D + jc * 4];
            float hk = hr[k];
            acc.x += hk * w.x; acc.y += hk * w.y;
            acc.z += hk * w.z; acc.w += hk * w.w;
        }
        mid[jc * 4 + 0] = fmaxf(acc.x, 0.f);
        mid[jc * 4 + 1] = fmaxf(acc.y, 0.f);
        mid[jc * 4 + 2] = fmaxf(acc.z, 0.f);
        mid[jc * 4 + 3] = fmaxf(acc.w, 0.f);
    }

    const float4* frow = (const float4*)(feat + (size_t)node * D);
    float4* orow = (float4*)(out + (size_t)node * D);
#pragma unroll
    for (int jc = 0; jc < D / 4; jc++) {
        float4 acc = *(const float4*)&s_b2[jc * 4];
#pragma unroll
        for (int k = 0; k < D; k++) {
            float4 w = *(const float4*)&s_w2[k * D + jc * 4];
            float mk = mid[k];
            acc.x += mk * w.x; acc.y += mk * w.y;
            acc.z += mk * w.z; acc.w += mk * w.w;
        }
        float4 f = frow[jc];
        orow[jc] = make_float4(acc.x + f.x, acc.y + f.y, acc.z + f.z, acc.w + f.w);
    }
}

// ---------------------------------------------------------------------
extern "C" void kernel_launch(void* const* d_in, const int* in_sizes, int n_in,
                              void* d_out, int out_size) {
    const float* feat = (const float*)d_in[0];
    const int*   src  = (const int*)d_in[1];
    const int*   dst  = (const int*)d_in[2];
    const float* w1   = (const float*)d_in[3];
    const float* b1   = (const float*)d_in[4];
    const float* w2   = (const float*)d_in[5];
    const float* b2   = (const float*)d_in[6];
    float* out = (float*)d_out;

    float* out_rst = out;                    // first output: rst [NN, D]
    float* out_r   = out + (size_t)NN * D;   // second output: r  [NN, D]

    const int T = 256;
    int gN  = (NN + T - 1) / T;
    int gE  = (NE + T - 1) / T;
    int gI  = ((NN + 1) * D2 + T - 1) / T;
    int gW  = (NN * 32 + T - 1) / T;         // warp-per-node grid

    // ---- CSR build (segments padded to multiples of 4) ----
    k_zero_deg<<<gN, T>>>();
    k_hist<<<gE, T>>>(dst);
    k_scan1<<<SCAN_BLKS, 1024>>>();
    k_scan3<<<(NN + 1 + T - 1) / T, T>>>();
    k_scatter<<<gE, T>>>(src, dst);
    k_initpad<<<gI, T>>>((const float2*)feat);

    // ---- propagation ----
    for (int hop = 0; hop < HOPS; hop++) {
        int rb = hop & 1;
        if (hop == HOPS - 1) {
            if (rb) k_prop<1, 1><<<gW, T>>>((const float2*)feat, (float2*)out_r);
            else    k_prop<1, 0><<<gW, T>>>((const float2*)feat, (float2*)out_r);
        } else {
            if (rb) k_prop<0, 1><<<gW, T>>>((const float2*)feat, (float2*)out_r);
            else    k_prop<0, 0><<<gW, T>>>((const float2*)feat, (float2*)out_r);
        }
    }

    // ---- FFN + residual ----
    const int TF = 128;
    k_ffn<<<(NN + TF - 1) / TF, TF>>>(out_r, feat, w1, b1, w2, b2, out_rst);
}